// round 6
// baseline (speedup 1.0000x reference)
#include <cuda_runtime.h>

// SampleQueryExtractionLayer: the relu(1 - L1(p,grid) + eps)^2 mask is
// 2-SPARSE: corner L1 distances obey d00+d11 = 2 and d01+d10 = 2, so at most
// one corner per diagonal pair is inside the unit L1 ball. Only the nearer
// of {(y0,x0),(y0+1,x0+1)} and the nearer of {(y0,x0+1),(y0+1,x0)} carry
// weight; dropped taps contribute <= eps^2 = 1e-8 (denominator >= eps = 1e-4
// => <= 1e-4 relative effect, inside the 1e-3 budget).
//
// features: [B=4, N=4096(=64x64), C=256] fp32; query_points: [4,8,256,2];
// out: [8192, 256] fp32. Single wave: 2048 blocks x 128 threads, each
// 64-thread group handles queries g and g+4096; all 4 tap-loads (2 per
// query) are front-batched.

#define EPS_F 0.0001f

struct Taps {
    int   offA, offB;    // float offsets of the two tap rows
    float wA, wB;        // unnormalized weights (normalization deferred)
    float inv;           // 1 / (wA + wB + eps)
};

__device__ __forceinline__ Taps make_taps(float2 p, int g)
{
    const int y0 = __float2int_rd(p.x);
    const int x0 = __float2int_rd(p.y);
    const float dy = p.x - (float)y0;
    const float dx = p.y - (float)x0;

    // Diagonal pair: nearer of (y0,x0) [d=dy+dx] and (y0+1,x0+1) [d=2-dy-dx]
    const float s  = dy + dx;
    const bool  a00 = (s <= 1.0f);
    const float mA  = (a00 ? (1.0f - s) : (s - 1.0f)) + EPS_F;   // > 0
    // Anti-diagonal pair: nearer of (y0,x0+1) [d=dy+1-dx] and (y0+1,x0) [d=1-dy+dx]
    const bool  b01 = (dx >= dy);
    const float mB  = (b01 ? (dx - dy) : (dy - dx)) + EPS_F;     // > 0

    const int base = (g >> 11) * 4096 + y0 * 64 + x0;            // cell (y0,x0)
    Taps t;
    t.offA = (a00 ? base : base + 65) * 256;                     // +65 = (+1,+1)
    t.offB = (b01 ? base + 1 : base + 64) * 256;
    t.wA = mA * mA;
    t.wB = mB * mB;
    t.inv = __fdividef(1.0f, t.wA + t.wB + EPS_F);
    return t;
}

__global__ __launch_bounds__(128)
void sqe_kernel(const float* __restrict__ feat,
                const float* __restrict__ qp,
                float* __restrict__ out)
{
    const int tid = threadIdx.x;
    const int grp = blockIdx.x * 2 + (tid >> 6);   // 0..4095
    const int c4  = tid & 63;                      // float4 lane in channel dim

    const int q0 = grp;                            // batches 0-1
    const int q1 = grp + 4096;                     // batches 2-3

    // Both query points issue immediately (independent loads, broadcast).
    const float2 p0 = __ldg(((const float2*)qp) + q0);
    const float2 p1 = __ldg(((const float2*)qp) + q1);

    const Taps t0 = make_taps(p0, q0);
    const Taps t1 = make_taps(p1, q1);

    const float4* f4 = (const float4*)feat;
    // Front-batch all 4 independent tap loads (16 data regs).
    const float4 f0A = __ldg(f4 + (t0.offA >> 2) + c4);
    const float4 f0B = __ldg(f4 + (t0.offB >> 2) + c4);
    const float4 f1A = __ldg(f4 + (t1.offA >> 2) + c4);
    const float4 f1B = __ldg(f4 + (t1.offB >> 2) + c4);

    float4 acc0, acc1;
    acc0.x = (t0.wA * f0A.x + t0.wB * f0B.x) * t0.inv;
    acc0.y = (t0.wA * f0A.y + t0.wB * f0B.y) * t0.inv;
    acc0.z = (t0.wA * f0A.z + t0.wB * f0B.z) * t0.inv;
    acc0.w = (t0.wA * f0A.w + t0.wB * f0B.w) * t0.inv;

    acc1.x = (t1.wA * f1A.x + t1.wB * f1B.x) * t1.inv;
    acc1.y = (t1.wA * f1A.y + t1.wB * f1B.y) * t1.inv;
    acc1.z = (t1.wA * f1A.z + t1.wB * f1B.z) * t1.inv;
    acc1.w = (t1.wA * f1A.w + t1.wB * f1B.w) * t1.inv;

    // Evict-first stores: keep the feature matrix resident in L2.
    __stcs(((float4*)out) + (size_t)q0 * 64 + c4, acc0);
    __stcs(((float4*)out) + (size_t)q1 * 64 + c4, acc1);
}

extern "C" void kernel_launch(void* const* d_in, const int* in_sizes, int n_in,
                              void* d_out, int out_size)
{
    (void)in_sizes; (void)n_in; (void)out_size;
    const float* feat = (const float*)d_in[0];
    const float* qp   = (const float*)d_in[1];
    float* out        = (float*)d_out;

    // 4096 query-groups, 2 per 128-thread block -> 2048 blocks, single wave.
    sqe_kernel<<<2048, 128>>>(feat, qp, out);
}